// round 1
// baseline (speedup 1.0000x reference)
#include <cuda_runtime.h>
#include <cuda_bf16.h>
#include <cstdint>

// Problem constants
#define T_SEQ 65536
#define F_IN  512
#define H_DIM 64
#define G_DIM 256   // 4*H

// Scratch (allocation-free rule: __device__ globals)
__device__ __align__(16) float g_xg[(size_t)T_SEQ * G_DIM];   // 64 MB input-projection
__device__ float g_hfin[H_DIM];

// ---------------- packed f32x2 helpers ----------------
__device__ __forceinline__ unsigned long long fma2(unsigned long long a,
                                                   unsigned long long b,
                                                   unsigned long long c) {
    unsigned long long d;
    asm("fma.rn.f32x2 %0, %1, %2, %3;" : "=l"(d) : "l"(a), "l"(b), "l"(c));
    return d;
}
__device__ __forceinline__ float2 upk(unsigned long long a) {
    float2 r;
    asm("mov.b64 {%0, %1}, %2;" : "=f"(r.x), "=f"(r.y) : "l"(a));
    return r;
}

// ---------------- fast-but-accurate activations (MUFU EX2 + RCP) ----------------
__device__ __forceinline__ float f_ex2(float x) { float r; asm("ex2.approx.f32 %0, %1;" : "=f"(r) : "f"(x)); return r; }
__device__ __forceinline__ float f_rcp(float x) { float r; asm("rcp.approx.f32 %0, %1;" : "=f"(r) : "f"(x)); return r; }
// sigmoid(x) = 1/(1+exp(-x)) = 1/(1+2^(-x*log2(e)))
__device__ __forceinline__ float sigm(float x) {
    return f_rcp(1.0f + f_ex2(-1.4426950408889634f * x));
}
// tanh(x) = 2*sigmoid(2x)-1
__device__ __forceinline__ float tanh_(float x) {
    return fmaf(2.0f, f_rcp(1.0f + f_ex2(-2.8853900817779268f * x)), -1.0f);
}

// =====================================================================
// Kernel 1: xg[t][j] = sum_k x[t][k] * W_ih[j][k] + (b_ih[j] + b_hh[j])
// Classic smem-tiled SGEMM, BM=BN=64, BK=16, 256 threads, TM=TN=4.
// =====================================================================
__global__ void gemm_xg(const float* __restrict__ x,
                        const float* __restrict__ Wih,
                        const float* __restrict__ bih,
                        const float* __restrict__ bhh) {
    __shared__ float xs[64][17];
    __shared__ float ws[64][17];
    const int tid = threadIdx.x;           // 0..255
    const int tx = tid & 15, ty = tid >> 4;
    const int row0 = blockIdx.x * 64;
    const int col0 = blockIdx.y * 64;

    float acc[4][4];
#pragma unroll
    for (int i = 0; i < 4; i++)
#pragma unroll
        for (int j = 0; j < 4; j++) acc[i][j] = 0.0f;

    const int l = tid * 4;
    const int lr = l >> 4, lk = l & 15;

    for (int kb = 0; kb < F_IN; kb += 16) {
        float4 xv = *(const float4*)(x + (size_t)(row0 + lr) * F_IN + kb + lk);
        float4 wv = *(const float4*)(Wih + (size_t)(col0 + lr) * F_IN + kb + lk);
        xs[lr][lk] = xv.x; xs[lr][lk + 1] = xv.y; xs[lr][lk + 2] = xv.z; xs[lr][lk + 3] = xv.w;
        ws[lr][lk] = wv.x; ws[lr][lk + 1] = wv.y; ws[lr][lk + 2] = wv.z; ws[lr][lk + 3] = wv.w;
        __syncthreads();
#pragma unroll
        for (int kk = 0; kk < 16; kk++) {
            float a[4], b[4];
#pragma unroll
            for (int i = 0; i < 4; i++) a[i] = xs[ty * 4 + i][kk];
#pragma unroll
            for (int j = 0; j < 4; j++) b[j] = ws[tx * 4 + j][kk];
#pragma unroll
            for (int i = 0; i < 4; i++)
#pragma unroll
                for (int j = 0; j < 4; j++) acc[i][j] = fmaf(a[i], b[j], acc[i][j]);
        }
        __syncthreads();
    }

#pragma unroll
    for (int j = 0; j < 4; j++) {
        const int col = col0 + tx * 4 + j;
        const float bj = bih[col] + bhh[col];
#pragma unroll
        for (int i = 0; i < 4; i++) {
            const int row = row0 + ty * 4 + i;
            g_xg[(size_t)row * G_DIM + col] = acc[i][j] + bj;
        }
    }
}

// =====================================================================
// Kernel 2: persistent single-block LSTM recurrence.
// 256 threads; thread j computes gate preactivation j each step via
// packed fma.rn.f32x2 against its register-resident W_hh row.
// =====================================================================
__global__ void __launch_bounds__(256, 1)
lstm_rec(const float* __restrict__ Whh,
         const float* __restrict__ h0,
         const float* __restrict__ c0) {
    __shared__ __align__(16) float h_sh[H_DIM];
    __shared__ float act[G_DIM];
    const int tid = threadIdx.x;     // 0..255 == gate-preact index j

    // W_hh row j -> 32 packed f32x2 register pairs (one-time, uncoalesced OK)
    unsigned long long w[32];
    {
        const ulonglong2* wr = (const ulonglong2*)(Whh + (size_t)tid * H_DIM);
#pragma unroll
        for (int i = 0; i < 16; i++) {
            ulonglong2 v = wr[i];
            w[2 * i] = v.x;
            w[2 * i + 1] = v.y;
        }
    }

    float c = 0.0f;
    if (tid < H_DIM) {
        h_sh[tid] = h0[tid];
        c = c0[tid];
    }

    // Register ring prefetch of xg (depth 4 ~ 1000+ cyc ahead of use)
    float xbuf[4];
#pragma unroll
    for (int p = 0; p < 4; p++) xbuf[p] = g_xg[(size_t)p * G_DIM + tid];

    for (int t = 0; t < T_SEQ; t++) {
        __syncthreads();   // h_sh[t] visible to all (bar A)

        // g[j] = xg[t][j] + sum_k h[k]*W_hh[j][k]  (32x fma.f32x2, 2 acc chains)
        unsigned long long a0 = 0ull, a1 = 0ull;
        const ulonglong2* hp = (const ulonglong2*)h_sh;
#pragma unroll
        for (int i = 0; i < 16; i++) {
            ulonglong2 hv = hp[i];             // LDS.128, warp-broadcast
            a0 = fma2(hv.x, w[2 * i], a0);
            a1 = fma2(hv.y, w[2 * i + 1], a1);
        }
        float2 s0 = upk(a0), s1 = upk(a1);
        float g = xbuf[t & 3] + ((s0.x + s0.y) + (s1.x + s1.y));

        // prefetch t+4
        const int tp = t + 4;
        if (tp < T_SEQ) xbuf[t & 3] = g_xg[(size_t)tp * G_DIM + tid];

        // gate nonlinearity: j in [0,64)=i [64,128)=f [128,192)=g(tanh) [192,256)=o
        act[tid] = ((tid >> 6) == 2) ? tanh_(g) : sigm(g);
        __syncthreads();   // activations visible (bar B)

        if (tid < H_DIM) {
            const float ai = act[tid];
            const float af = act[H_DIM + tid];
            const float ag = act[2 * H_DIM + tid];
            const float ao = act[3 * H_DIM + tid];
            c = fmaf(af, c, ai * ag);
            h_sh[tid] = ao * tanh_(c);
        }
    }

    __syncthreads();
    if (tid < H_DIM) g_hfin[tid] = h_sh[tid];
}

// =====================================================================
// Kernel 3: out[f] = sigmoid(h_last . W_fc[f] + b_fc[f]),  f < 512
// =====================================================================
__global__ void fc_out(const float* __restrict__ Wfc,
                       const float* __restrict__ bfc,
                       float* __restrict__ out) {
    __shared__ float h[H_DIM];
    const int tid = threadIdx.x;   // 0..511
    if (tid < H_DIM) h[tid] = g_hfin[tid];
    __syncthreads();
    float acc = bfc[tid];
    const float* wr = Wfc + (size_t)tid * H_DIM;
#pragma unroll
    for (int k = 0; k < H_DIM; k++) acc = fmaf(wr[k], h[k], acc);
    out[tid] = 1.0f / (1.0f + __expf(-acc));
}

extern "C" void kernel_launch(void* const* d_in, const int* in_sizes, int n_in,
                              void* d_out, int out_size) {
    const float* x   = (const float*)d_in[0];
    const float* h0  = (const float*)d_in[1];
    const float* c0  = (const float*)d_in[2];
    const float* Wih = (const float*)d_in[3];
    const float* Whh = (const float*)d_in[4];
    const float* bih = (const float*)d_in[5];
    const float* bhh = (const float*)d_in[6];
    const float* Wfc = (const float*)d_in[7];
    const float* bfc = (const float*)d_in[8];
    float* out = (float*)d_out;

    dim3 ggrid(T_SEQ / 64, G_DIM / 64);
    gemm_xg<<<ggrid, 256>>>(x, Wih, bih, bhh);
    lstm_rec<<<1, 256>>>(Whh, h0, c0);
    fc_out<<<1, 512>>>(Wfc, bfc, out);
}

// round 2
// speedup vs baseline: 1.8207x; 1.8207x over previous
#include <cuda_runtime.h>
#include <cuda_bf16.h>
#include <cstdint>

// Problem constants
#define T_SEQ 65536
#define F_IN  512
#define H_DIM 64
#define G_DIM 256   // 4*H
#define NT    (T_SEQ / 4)

// Scratch (allocation-free rule: __device__ globals)
// Blocked + permuted input projection: [T/4][256 threads][4 sub-steps] as float4
__device__ __align__(16) float4 g_xg4[(size_t)NT * G_DIM];
__device__ float g_hfin[H_DIM];

// ---------------- packed f32x2 helpers ----------------
static __device__ __forceinline__ unsigned long long fma2(unsigned long long a,
                                                          unsigned long long b,
                                                          unsigned long long c) {
    unsigned long long d;
    asm("fma.rn.f32x2 %0, %1, %2, %3;" : "=l"(d) : "l"(a), "l"(b), "l"(c));
    return d;
}
static __device__ __forceinline__ unsigned long long add2(unsigned long long a,
                                                          unsigned long long b) {
    unsigned long long d;
    asm("add.rn.f32x2 %0, %1, %2;" : "=l"(d) : "l"(a), "l"(b));
    return d;
}
static __device__ __forceinline__ float2 upk(unsigned long long a) {
    float2 r;
    asm("mov.b64 {%0, %1}, %2;" : "=f"(r.x), "=f"(r.y) : "l"(a));
    return r;
}

// ---------------- MUFU activations ----------------
static __device__ __forceinline__ float f_ex2(float x) { float r; asm("ex2.approx.f32 %0, %1;" : "=f"(r) : "f"(x)); return r; }
static __device__ __forceinline__ float f_rcp(float x) { float r; asm("rcp.approx.f32 %0, %1;" : "=f"(r) : "f"(x)); return r; }
static __device__ __forceinline__ float tanh_(float x) {
    // tanh(x) = 2*sigmoid(2x) - 1
    return fmaf(2.0f, f_rcp(1.0f + f_ex2(-2.8853900817779268f * x)), -1.0f);
}

// =====================================================================
// Kernel 1: xg = x @ W_ih.T + (b_ih + b_hh), written in blocked/permuted
// layout for the recurrence: g_xg4[tblk*256 + p(col)] = {t0,t1,t2,t3}
// where p maps gate-row col -> recurrence thread id.
// =====================================================================
__global__ void gemm_xg(const float* __restrict__ x,
                        const float* __restrict__ Wih,
                        const float* __restrict__ bih,
                        const float* __restrict__ bhh) {
    __shared__ float xs[64][17];
    __shared__ float ws[64][17];
    const int tid = threadIdx.x;           // 0..255
    const int tx = tid & 15, ty = tid >> 4;
    const int row0 = blockIdx.x * 64;      // t-tile base (multiple of 64)
    const int col0 = blockIdx.y * 64;      // gate-row tile base

    float acc[4][4];
#pragma unroll
    for (int i = 0; i < 4; i++)
#pragma unroll
        for (int j = 0; j < 4; j++) acc[i][j] = 0.0f;

    const int l = tid * 4;
    const int lr = l >> 4, lk = l & 15;

    for (int kb = 0; kb < F_IN; kb += 16) {
        float4 xv = *(const float4*)(x + (size_t)(row0 + lr) * F_IN + kb + lk);
        float4 wv = *(const float4*)(Wih + (size_t)(col0 + lr) * F_IN + kb + lk);
        xs[lr][lk] = xv.x; xs[lr][lk + 1] = xv.y; xs[lr][lk + 2] = xv.z; xs[lr][lk + 3] = xv.w;
        ws[lr][lk] = wv.x; ws[lr][lk + 1] = wv.y; ws[lr][lk + 2] = wv.z; ws[lr][lk + 3] = wv.w;
        __syncthreads();
#pragma unroll
        for (int kk = 0; kk < 16; kk++) {
            float a[4], b[4];
#pragma unroll
            for (int i = 0; i < 4; i++) a[i] = xs[ty * 4 + i][kk];
#pragma unroll
            for (int j = 0; j < 4; j++) b[j] = ws[tx * 4 + j][kk];
#pragma unroll
            for (int i = 0; i < 4; i++)
#pragma unroll
                for (int j = 0; j < 4; j++) acc[i][j] = fmaf(a[i], b[j], acc[i][j]);
        }
        __syncthreads();
    }

    // Epilogue: this thread's 4 rows are t = row0+ty*4 .. +3 -> one tblk
    const int tblk = (row0 >> 2) + ty;
#pragma unroll
    for (int j = 0; j < 4; j++) {
        const int col = col0 + tx * 4 + j;
        const float bj = bih[col] + bhh[col];
        const int gg = col >> 6;            // gate index 0..3 (constant per block)
        const int uu = col & 63;            // hidden unit
        const int p = ((uu >> 3) << 5) + ((uu & 7) << 2) + gg;  // recurrence tid
        float4 o;
        o.x = acc[0][j] + bj;
        o.y = acc[1][j] + bj;
        o.z = acc[2][j] + bj;
        o.w = acc[3][j] + bj;
        g_xg4[(size_t)tblk * G_DIM + p] = o;
    }
}

// =====================================================================
// Kernel 2: persistent single-block LSTM recurrence.
// 256 threads. Warp w owns hidden units [8w, 8w+8); lane l computes the
// preactivation of gate (l%4) for unit (8w + l/4). All 4 gates of a unit
// live in one warp -> gate exchange is intra-warp (smem + syncwarp), and
// only the h broadcast needs one __syncthreads per step (double-buffered).
// =====================================================================
__global__ void __launch_bounds__(256, 1)
lstm_rec(const float* __restrict__ Whh,
         const float* __restrict__ h0,
         const float* __restrict__ c0) {
    __shared__ __align__(16) float h_sh[2][H_DIM];
    __shared__ __align__(16) float act_sh[G_DIM];
    const int tid = threadIdx.x;          // == xg permuted index p
    const int w = tid >> 5, l = tid & 31;
    const int u = w * 8 + (l >> 2);       // hidden unit
    const int g = l & 3;                  // gate: 0=i 1=f 2=g(tanh) 3=o
    const int r = (g << 6) | u;           // row in W_hh / gate-preact index
    const bool g0 = (g == 0);

    // W_hh row r -> 32 packed f32x2 register pairs
    unsigned long long wreg[32];
    {
        const ulonglong2* wr = (const ulonglong2*)(Whh + (size_t)r * H_DIM);
#pragma unroll
        for (int i = 0; i < 16; i++) {
            ulonglong2 v = wr[i];
            wreg[2 * i] = v.x;
            wreg[2 * i + 1] = v.y;
        }
    }

    // Branchless activation constants (tanh for g==2, sigmoid otherwise)
    const float scl = (g == 2) ? 2.0f : 1.0f;
    const float kls = -1.4426950408889634f * scl;
    const float ofs = scl - 1.0f;

    float c = 0.0f, h = 0.0f;
    if (g0) {
        c = c0[u];
        h = h0[u];
        h_sh[0][u] = h;
    }
    __syncthreads();

#define SUBSTEP(XV, RB, WB) do {                                              \
        const ulonglong2* hp = (const ulonglong2*)h_sh[RB];                   \
        unsigned long long a0 = 0ull, a1 = 0ull, a2 = 0ull, a3 = 0ull;        \
        _Pragma("unroll")                                                     \
        for (int i = 0; i < 8; i++) {                                         \
            ulonglong2 h01 = hp[2 * i];                                       \
            ulonglong2 h23 = hp[2 * i + 1];                                   \
            a0 = fma2(h01.x, wreg[4 * i + 0], a0);                            \
            a1 = fma2(h01.y, wreg[4 * i + 1], a1);                            \
            a2 = fma2(h23.x, wreg[4 * i + 2], a2);                            \
            a3 = fma2(h23.y, wreg[4 * i + 3], a3);                            \
        }                                                                     \
        float2 s = upk(add2(add2(a0, a1), add2(a2, a3)));                     \
        float pre = (XV) + s.x + s.y;                                         \
        float y = f_rcp(1.0f + f_ex2(kls * pre));                             \
        act_sh[tid] = fmaf(scl, y, -ofs);                                     \
        __syncwarp();                                                         \
        if (g0) {                                                             \
            float4 a4 = *(const float4*)&act_sh[tid]; /* {i,f,g,o} of unit */ \
            c = fmaf(a4.y, c, a4.x * a4.z);                                   \
            h = a4.w * tanh_(c);                                              \
            h_sh[WB][u] = h;                                                  \
        }                                                                     \
        __syncthreads();                                                      \
    } while (0)

    // Software-pipelined xg stream: one coalesced LDG.128 per 4 steps,
    // prefetched 2 blocks (~8 steps) ahead. All ring slots are named regs.
    float4 xa = g_xg4[tid];
    float4 xb = g_xg4[G_DIM + tid];
    for (int tb = 0; tb < NT; tb++) {
        float4 xc = xb;
        if (tb + 2 < NT) xc = g_xg4[(size_t)(tb + 2) * G_DIM + tid];
        SUBSTEP(xa.x, 0, 1);
        SUBSTEP(xa.y, 1, 0);
        SUBSTEP(xa.z, 0, 1);
        SUBSTEP(xa.w, 1, 0);
        xa = xb;
        xb = xc;
    }
#undef SUBSTEP

    if (g0) g_hfin[u] = h;
}

// =====================================================================
// Kernel 3: out[f] = sigmoid(h_last . W_fc[f] + b_fc[f]),  f < 512
// =====================================================================
__global__ void fc_out(const float* __restrict__ Wfc,
                       const float* __restrict__ bfc,
                       float* __restrict__ out) {
    __shared__ float hsm[H_DIM];
    const int tid = threadIdx.x;   // 0..511
    if (tid < H_DIM) hsm[tid] = g_hfin[tid];
    __syncthreads();
    float acc = bfc[tid];
    const float* wr = Wfc + (size_t)tid * H_DIM;
#pragma unroll
    for (int k = 0; k < H_DIM; k++) acc = fmaf(wr[k], hsm[k], acc);
    out[tid] = 1.0f / (1.0f + __expf(-acc));
}

extern "C" void kernel_launch(void* const* d_in, const int* in_sizes, int n_in,
                              void* d_out, int out_size) {
    const float* x   = (const float*)d_in[0];
    const float* h0  = (const float*)d_in[1];
    const float* c0  = (const float*)d_in[2];
    const float* Wih = (const float*)d_in[3];
    const float* Whh = (const float*)d_in[4];
    const float* bih = (const float*)d_in[5];
    const float* bhh = (const float*)d_in[6];
    const float* Wfc = (const float*)d_in[7];
    const float* bfc = (const float*)d_in[8];
    float* out = (float*)d_out;

    dim3 ggrid(T_SEQ / 64, G_DIM / 64);
    gemm_xg<<<ggrid, 256>>>(x, Wih, bih, bhh);
    lstm_rec<<<1, 256>>>(Whh, h0, c0);
    fc_out<<<1, 512>>>(Wfc, bfc, out);
}

// round 3
// speedup vs baseline: 2.1456x; 1.1784x over previous
#include <cuda_runtime.h>
#include <cuda_bf16.h>
#include <cstdint>

// Problem constants
#define T_SEQ 65536
#define F_IN  512
#define H_DIM 64
#define G_DIM 256    // 4*H
#define NT2   (T_SEQ / 2)

typedef unsigned long long ull;

// Scratch (allocation-free rule: __device__ globals)
// xg split into slot-A / slot-B streams for the recurrence thread mapping:
// g_xgA[tb*128 + tid] = {preA(2tb), preA(2tb+1)} for recurrence thread tid.
__device__ __align__(16) float2 g_xgA[(size_t)NT2 * 128];
__device__ __align__(16) float2 g_xgB[(size_t)NT2 * 128];
__device__ float g_hfin[H_DIM];

// ---------------- packed f32x2 helpers ----------------
static __device__ __forceinline__ ull fma2(ull a, ull b, ull c) {
    ull d;
    asm("fma.rn.f32x2 %0, %1, %2, %3;" : "=l"(d) : "l"(a), "l"(b), "l"(c));
    return d;
}
static __device__ __forceinline__ ull add2(ull a, ull b) {
    ull d;
    asm("add.rn.f32x2 %0, %1, %2;" : "=l"(d) : "l"(a), "l"(b));
    return d;
}
static __device__ __forceinline__ float2 upk(ull a) {
    float2 r;
    asm("mov.b64 {%0, %1}, %2;" : "=f"(r.x), "=f"(r.y) : "l"(a));
    return r;
}

// ---------------- MUFU activations ----------------
static __device__ __forceinline__ float f_ex2(float x) { float r; asm("ex2.approx.f32 %0, %1;" : "=f"(r) : "f"(x)); return r; }
static __device__ __forceinline__ float f_rcp(float x) { float r; asm("rcp.approx.f32 %0, %1;" : "=f"(r) : "f"(x)); return r; }
static __device__ __forceinline__ float tanh_(float x) {
    // tanh(x) = 2*sigmoid(2x) - 1
    return fmaf(2.0f, f_rcp(1.0f + f_ex2(-2.8853900817779268f * x)), -1.0f);
}

// Recurrence thread mapping for gate-row r (= g*64 + u):
// warp w = u>>4 owns units [16w,16w+16); pair p = u&15; lane = 2p + odd
// even lane: gates i (slot A), g (slot B); odd lane: gates f (A), o (B)
static __device__ __forceinline__ int map_tid(int g, int u) {
    int odd = g & 1;                 // i,g -> even ; f,o -> odd (g codes 0,2 even / 1,3 odd)
    return ((u >> 4) << 5) + ((u & 15) << 1) + odd;
}

// =====================================================================
// Kernel 1: xg = x @ W_ih.T + (b_ih + b_hh), written permuted into the
// two recurrence slot streams.
// =====================================================================
__global__ void gemm_xg(const float* __restrict__ x,
                        const float* __restrict__ Wih,
                        const float* __restrict__ bih,
                        const float* __restrict__ bhh) {
    __shared__ float xs[64][17];
    __shared__ float ws[64][17];
    const int tid = threadIdx.x;           // 0..255
    const int tx = tid & 15, ty = tid >> 4;
    const int row0 = blockIdx.x * 64;      // t-tile base
    const int col0 = blockIdx.y * 64;      // gate-row tile base

    float acc[4][4];
#pragma unroll
    for (int i = 0; i < 4; i++)
#pragma unroll
        for (int j = 0; j < 4; j++) acc[i][j] = 0.0f;

    const int l = tid * 4;
    const int lr = l >> 4, lk = l & 15;

    for (int kb = 0; kb < F_IN; kb += 16) {
        float4 xv = *(const float4*)(x + (size_t)(row0 + lr) * F_IN + kb + lk);
        float4 wv = *(const float4*)(Wih + (size_t)(col0 + lr) * F_IN + kb + lk);
        xs[lr][lk] = xv.x; xs[lr][lk + 1] = xv.y; xs[lr][lk + 2] = xv.z; xs[lr][lk + 3] = xv.w;
        ws[lr][lk] = wv.x; ws[lr][lk + 1] = wv.y; ws[lr][lk + 2] = wv.z; ws[lr][lk + 3] = wv.w;
        __syncthreads();
#pragma unroll
        for (int kk = 0; kk < 16; kk++) {
            float a[4], b[4];
#pragma unroll
            for (int i = 0; i < 4; i++) a[i] = xs[ty * 4 + i][kk];
#pragma unroll
            for (int j = 0; j < 4; j++) b[j] = ws[tx * 4 + j][kk];
#pragma unroll
            for (int i = 0; i < 4; i++)
#pragma unroll
                for (int j = 0; j < 4; j++) acc[i][j] = fmaf(a[i], b[j], acc[i][j]);
        }
        __syncthreads();
    }

    // Epilogue: rows t0..t0+3 (t0 multiple of 4) -> timestep-pairs tb0, tb0+1
    const int t0 = row0 + ty * 4;
    const int tb0 = t0 >> 1;
#pragma unroll
    for (int j = 0; j < 4; j++) {
        const int col = col0 + tx * 4 + j;
        const float bj = bih[col] + bhh[col];
        const int gg = col >> 6;            // gate 0=i 1=f 2=g 3=o
        const int uu = col & 63;
        const int p = map_tid(gg, uu);
        float2 lo = make_float2(acc[0][j] + bj, acc[1][j] + bj);
        float2 hi = make_float2(acc[2][j] + bj, acc[3][j] + bj);
        float2* buf = (gg >= 2) ? g_xgB : g_xgA;   // slot B = gates g,o
        buf[(size_t)tb0 * 128 + p] = lo;
        buf[(size_t)(tb0 + 1) * 128 + p] = hi;
    }
}

// =====================================================================
// Kernel 2: persistent single-block LSTM recurrence, 128 threads.
// Thread = (unit u, lane-parity): even lane computes gates (i, g) of u,
// odd lane computes (f, o). 2 W_hh rows in registers per thread.
// One __syncthreads per step; gate exchange via a single shfl.
// =====================================================================
__global__ void __launch_bounds__(128, 1)
lstm_rec(const float* __restrict__ Whh,
         const float* __restrict__ h0,
         const float* __restrict__ c0) {
    __shared__ __align__(16) float h_sh[2][H_DIM];
    const int tid = threadIdx.x;          // 0..127
    const int w = tid >> 5, l = tid & 31;
    const int u = (w << 4) + (l >> 1);    // hidden unit
    const int odd = l & 1;
    const int rA = (odd ? 64 : 0) + u;    // i or f
    const int rB = (odd ? 192 : 128) + u; // g or o

    // W_hh rows -> packed f32x2 registers
    ull wA[32], wB[32];
    {
        const ulonglong2* pa = (const ulonglong2*)(Whh + (size_t)rA * H_DIM);
        const ulonglong2* pb = (const ulonglong2*)(Whh + (size_t)rB * H_DIM);
#pragma unroll
        for (int i = 0; i < 16; i++) {
            ulonglong2 va = pa[i], vb = pb[i];
            wA[2 * i] = va.x; wA[2 * i + 1] = va.y;
            wB[2 * i] = vb.x; wB[2 * i + 1] = vb.y;
        }
    }

    // Slot-A is always sigmoid; slot-B is tanh on even lanes, sigmoid on odd
    const float KA = -1.4426950408889634f;
    const float sclB = odd ? 1.0f : 2.0f;
    const float KB = KA * sclB;
    const float ofsB = sclB - 1.0f;

    float c = odd ? c0[u] : 0.0f;
    float h = 0.0f;
    if (tid < H_DIM) h_sh[0][tid] = h0[tid];

#define STEP(XA, XB, RB, WB) do {                                             \
        __syncthreads();                                                      \
        const ulonglong2* hp = (const ulonglong2*)h_sh[RB];                   \
        ull a0 = 0, a1 = 0, a2 = 0, a3 = 0;                                   \
        ull b0 = 0, b1 = 0, b2 = 0, b3 = 0;                                   \
        _Pragma("unroll")                                                     \
        for (int i = 0; i < 8; i++) {                                         \
            ulonglong2 hv = hp[2 * i], hw = hp[2 * i + 1];                    \
            a0 = fma2(hv.x, wA[4 * i + 0], a0);                               \
            b0 = fma2(hv.x, wB[4 * i + 0], b0);                               \
            a1 = fma2(hv.y, wA[4 * i + 1], a1);                               \
            b1 = fma2(hv.y, wB[4 * i + 1], b1);                               \
            a2 = fma2(hw.x, wA[4 * i + 2], a2);                               \
            b2 = fma2(hw.x, wB[4 * i + 2], b2);                               \
            a3 = fma2(hw.y, wA[4 * i + 3], a3);                               \
            b3 = fma2(hw.y, wB[4 * i + 3], b3);                               \
        }                                                                     \
        float2 sA = upk(add2(add2(a0, a1), add2(a2, a3)));                    \
        float2 sB = upk(add2(add2(b0, b1), add2(b2, b3)));                    \
        float preA = (XA) + sA.x + sA.y;                                      \
        float preB = (XB) + sB.x + sB.y;                                      \
        float vA = f_rcp(1.0f + f_ex2(KA * preA));                            \
        float vB = fmaf(sclB, f_rcp(1.0f + f_ex2(KB * preB)), -ofsB);         \
        float pr = __shfl_sync(0xffffffffu, vA * vB, l & 30);  /* i*g */      \
        if (odd) {                                                            \
            c = fmaf(vA, c, pr);          /* c = f*c + i*g */                 \
            h = vB * tanh_(c);            /* h = o*tanh(c) */                 \
            h_sh[WB][u] = h;                                                  \
        }                                                                     \
    } while (0)

    // Streamed xg: one LDG.64 pair per 2 steps, prefetched 2 blocks ahead.
    float2 xA0 = g_xgA[tid],       xB0 = g_xgB[tid];
    float2 xA1 = g_xgA[128 + tid], xB1 = g_xgB[128 + tid];
    for (int tb = 0; tb < NT2; tb++) {
        float2 xA2 = xA1, xB2 = xB1;
        if (tb + 2 < NT2) {
            xA2 = g_xgA[(size_t)(tb + 2) * 128 + tid];
            xB2 = g_xgB[(size_t)(tb + 2) * 128 + tid];
        }
        STEP(xA0.x, xB0.x, 0, 1);
        STEP(xA0.y, xB0.y, 1, 0);
        xA0 = xA1; xA1 = xA2;
        xB0 = xB1; xB1 = xB2;
    }
#undef STEP

    if (odd) g_hfin[u] = h;
}

// =====================================================================
// Kernel 3: out[f] = sigmoid(h_last . W_fc[f] + b_fc[f]),  f < 512
// =====================================================================
__global__ void fc_out(const float* __restrict__ Wfc,
                       const float* __restrict__ bfc,
                       float* __restrict__ out) {
    __shared__ float hsm[H_DIM];
    const int tid = threadIdx.x;   // 0..511
    if (tid < H_DIM) hsm[tid] = g_hfin[tid];
    __syncthreads();
    float acc = bfc[tid];
    const float* wr = Wfc + (size_t)tid * H_DIM;
#pragma unroll
    for (int k = 0; k < H_DIM; k++) acc = fmaf(wr[k], hsm[k], acc);
    out[tid] = 1.0f / (1.0f + __expf(-acc));
}

extern "C" void kernel_launch(void* const* d_in, const int* in_sizes, int n_in,
                              void* d_out, int out_size) {
    const float* x   = (const float*)d_in[0];
    const float* h0  = (const float*)d_in[1];
    const float* c0  = (const float*)d_in[2];
    const float* Wih = (const float*)d_in[3];
    const float* Whh = (const float*)d_in[4];
    const float* bih = (const float*)d_in[5];
    const float* bhh = (const float*)d_in[6];
    const float* Wfc = (const float*)d_in[7];
    const float* bfc = (const float*)d_in[8];
    float* out = (float*)d_out;

    dim3 ggrid(T_SEQ / 64, G_DIM / 64);
    gemm_xg<<<ggrid, 256>>>(x, Wih, bih, bhh);
    lstm_rec<<<1, 128>>>(Whh, h0, c0);
    fc_out<<<1, 512>>>(Wfc, bfc, out);
}

// round 4
// speedup vs baseline: 2.4188x; 1.1273x over previous
#include <cuda_runtime.h>
#include <cuda_bf16.h>
#include <cstdint>

// Problem constants
#define T_SEQ 65536
#define F_IN  512
#define H_DIM 64
#define G_DIM 256    // 4*H
#define NT2   (T_SEQ / 2)

typedef unsigned long long ull;

// Scratch (allocation-free rule: __device__ globals)
__device__ __align__(16) float2 g_xgA[(size_t)NT2 * 128];
__device__ __align__(16) float2 g_xgB[(size_t)NT2 * 128];
__device__ float g_hfin[H_DIM];

// ---------------- packed f32x2 helpers ----------------
static __device__ __forceinline__ ull fma2(ull a, ull b, ull c) {
    ull d;
    asm("fma.rn.f32x2 %0, %1, %2, %3;" : "=l"(d) : "l"(a), "l"(b), "l"(c));
    return d;
}
static __device__ __forceinline__ ull add2(ull a, ull b) {
    ull d;
    asm("add.rn.f32x2 %0, %1, %2;" : "=l"(d) : "l"(a), "l"(b));
    return d;
}
static __device__ __forceinline__ float2 upk(ull a) {
    float2 r;
    asm("mov.b64 {%0, %1}, %2;" : "=f"(r.x), "=f"(r.y) : "l"(a));
    return r;
}

// ---------------- single-instruction MUFU.TANH ----------------
static __device__ __forceinline__ float tanhap(float x) {
    float r;
    asm("tanh.approx.f32 %0, %1;" : "=f"(r) : "f"(x));
    return r;
}

// Recurrence thread mapping for gate-row r (= g*64 + u):
// warp w = u>>4 owns units [16w,16w+16); even lane: gates (i,g); odd: (f,o)
static __device__ __forceinline__ int map_tid(int g, int u) {
    int odd = g & 1;                 // i,g -> even ; f,o -> odd
    return ((u >> 4) << 5) + ((u & 15) << 1) + odd;
}

// =====================================================================
// Kernel 1: xg = x @ W_ih.T + (b_ih + b_hh), permuted into slot streams.
// =====================================================================
__global__ void gemm_xg(const float* __restrict__ x,
                        const float* __restrict__ Wih,
                        const float* __restrict__ bih,
                        const float* __restrict__ bhh) {
    __shared__ float xs[64][17];
    __shared__ float ws[64][17];
    const int tid = threadIdx.x;           // 0..255
    const int tx = tid & 15, ty = tid >> 4;
    const int row0 = blockIdx.x * 64;      // t-tile base
    const int col0 = blockIdx.y * 64;      // gate-row tile base

    float acc[4][4];
#pragma unroll
    for (int i = 0; i < 4; i++)
#pragma unroll
        for (int j = 0; j < 4; j++) acc[i][j] = 0.0f;

    const int l = tid * 4;
    const int lr = l >> 4, lk = l & 15;

    for (int kb = 0; kb < F_IN; kb += 16) {
        float4 xv = *(const float4*)(x + (size_t)(row0 + lr) * F_IN + kb + lk);
        float4 wv = *(const float4*)(Wih + (size_t)(col0 + lr) * F_IN + kb + lk);
        xs[lr][lk] = xv.x; xs[lr][lk + 1] = xv.y; xs[lr][lk + 2] = xv.z; xs[lr][lk + 3] = xv.w;
        ws[lr][lk] = wv.x; ws[lr][lk + 1] = wv.y; ws[lr][lk + 2] = wv.z; ws[lr][lk + 3] = wv.w;
        __syncthreads();
#pragma unroll
        for (int kk = 0; kk < 16; kk++) {
            float a[4], b[4];
#pragma unroll
            for (int i = 0; i < 4; i++) a[i] = xs[ty * 4 + i][kk];
#pragma unroll
            for (int j = 0; j < 4; j++) b[j] = ws[tx * 4 + j][kk];
#pragma unroll
            for (int i = 0; i < 4; i++)
#pragma unroll
                for (int j = 0; j < 4; j++) acc[i][j] = fmaf(a[i], b[j], acc[i][j]);
        }
        __syncthreads();
    }

    const int t0 = row0 + ty * 4;
    const int tb0 = t0 >> 1;
#pragma unroll
    for (int j = 0; j < 4; j++) {
        const int col = col0 + tx * 4 + j;
        const float bj = bih[col] + bhh[col];
        const int gg = col >> 6;            // gate 0=i 1=f 2=g 3=o
        const int uu = col & 63;
        const int p = map_tid(gg, uu);
        float2 lo = make_float2(acc[0][j] + bj, acc[1][j] + bj);
        float2 hi = make_float2(acc[2][j] + bj, acc[3][j] + bj);
        float2* buf = (gg >= 2) ? g_xgB : g_xgA;   // slot B = gates g,o
        buf[(size_t)tb0 * 128 + p] = lo;
        buf[(size_t)(tb0 + 1) * 128 + p] = hi;
    }
}

// =====================================================================
// Kernel 2: persistent single-block LSTM recurrence, 128 threads.
// Even lane computes gates (i, g) of unit u, odd lane (f, o).
// One __syncthreads per step; gate product crosses via one shfl.
// All activations via single-instruction MUFU.TANH.
// =====================================================================
__global__ void __launch_bounds__(128, 1)
lstm_rec(const float* __restrict__ Whh,
         const float* __restrict__ h0,
         const float* __restrict__ c0) {
    __shared__ __align__(16) float h_sh[2][H_DIM];
    const int tid = threadIdx.x;          // 0..127
    const int w = tid >> 5, l = tid & 31;
    const int u = (w << 4) + (l >> 1);    // hidden unit
    const int odd = l & 1;
    const int rA = (odd ? 64 : 0) + u;    // i or f
    const int rB = (odd ? 192 : 128) + u; // g or o

    // W_hh rows -> packed f32x2 registers
    ull wA[32], wB[32];
    {
        const ulonglong2* pa = (const ulonglong2*)(Whh + (size_t)rA * H_DIM);
        const ulonglong2* pb = (const ulonglong2*)(Whh + (size_t)rB * H_DIM);
#pragma unroll
        for (int i = 0; i < 16; i++) {
            ulonglong2 va = pa[i], vb = pb[i];
            wA[2 * i] = va.x; wA[2 * i + 1] = va.y;
            wB[2 * i] = vb.x; wB[2 * i + 1] = vb.y;
        }
    }

    // Slot-A is always sigmoid: s(x) = 0.5*tanh(0.5x)+0.5
    // Slot-B: tanh on even lanes (gate g), sigmoid on odd lanes (gate o)
    const float aB  = odd ? 0.5f : 1.0f;
    const float oB  = odd ? 0.5f : 0.0f;

    float c = odd ? c0[u] : 0.0f;
    float h = 0.0f;
    if (tid < H_DIM) h_sh[0][tid] = h0[tid];

#define STEP(XA, XB, RB, WB) do {                                             \
        __syncthreads();                                                      \
        const ulonglong2* hp = (const ulonglong2*)h_sh[RB];                   \
        ull a0 = 0, a1 = 0, a2 = 0, a3 = 0;                                   \
        ull b0 = 0, b1 = 0, b2 = 0, b3 = 0;                                   \
        _Pragma("unroll")                                                     \
        for (int i = 0; i < 8; i++) {                                         \
            ulonglong2 hv = hp[2 * i], hw = hp[2 * i + 1];                    \
            a0 = fma2(hv.x, wA[4 * i + 0], a0);                               \
            b0 = fma2(hv.x, wB[4 * i + 0], b0);                               \
            a1 = fma2(hv.y, wA[4 * i + 1], a1);                               \
            b1 = fma2(hv.y, wB[4 * i + 1], b1);                               \
            a2 = fma2(hw.x, wA[4 * i + 2], a2);                               \
            b2 = fma2(hw.x, wB[4 * i + 2], b2);                               \
            a3 = fma2(hw.y, wA[4 * i + 3], a3);                               \
            b3 = fma2(hw.y, wB[4 * i + 3], b3);                               \
        }                                                                     \
        float2 sA = upk(add2(add2(a0, a1), add2(a2, a3)));                    \
        float2 sB = upk(add2(add2(b0, b1), add2(b2, b3)));                    \
        float preA = (XA) + sA.x + sA.y;                                      \
        float preB = (XB) + sB.x + sB.y;                                      \
        float vA = fmaf(0.5f, tanhap(0.5f * preA), 0.5f);   /* sigmoid */     \
        float vB = fmaf(aB, tanhap(aB * preB), oB);         /* tanh / sig */  \
        float pr = __shfl_sync(0xffffffffu, vA * vB, l & 30);  /* i*g~ */     \
        if (odd) {                                                            \
            c = fmaf(vA, c, pr);            /* c = f*c + i*g~ */              \
            h = vB * tanhap(c);             /* h = o*tanh(c) */               \
            h_sh[WB][u] = h;                                                  \
        }                                                                     \
    } while (0)

    // Streamed xg: one LDG.64 pair per 2 steps, prefetched 2 blocks ahead.
    float2 xA0 = g_xgA[tid],       xB0 = g_xgB[tid];
    float2 xA1 = g_xgA[128 + tid], xB1 = g_xgB[128 + tid];
    for (int tb = 0; tb < NT2; tb++) {
        float2 xA2 = xA1, xB2 = xB1;
        if (tb + 2 < NT2) {
            xA2 = g_xgA[(size_t)(tb + 2) * 128 + tid];
            xB2 = g_xgB[(size_t)(tb + 2) * 128 + tid];
        }
        STEP(xA0.x, xB0.x, 0, 1);
        STEP(xA0.y, xB0.y, 1, 0);
        xA0 = xA1; xA1 = xA2;
        xB0 = xB1; xB1 = xB2;
    }
#undef STEP

    if (odd) g_hfin[u] = h;
}

// =====================================================================
// Kernel 3: out[f] = sigmoid(h_last . W_fc[f] + b_fc[f]),  f < 512
// =====================================================================
__global__ void fc_out(const float* __restrict__ Wfc,
                       const float* __restrict__ bfc,
                       float* __restrict__ out) {
    __shared__ float hsm[H_DIM];
    const int tid = threadIdx.x;   // 0..511
    if (tid < H_DIM) hsm[tid] = g_hfin[tid];
    __syncthreads();
    float acc = bfc[tid];
    const float* wr = Wfc + (size_t)tid * H_DIM;
#pragma unroll
    for (int k = 0; k < H_DIM; k++) acc = fmaf(wr[k], hsm[k], acc);
    out[tid] = 1.0f / (1.0f + __expf(-acc));
}

extern "C" void kernel_launch(void* const* d_in, const int* in_sizes, int n_in,
                              void* d_out, int out_size) {
    const float* x   = (const float*)d_in[0];
    const float* h0  = (const float*)d_in[1];
    const float* c0  = (const float*)d_in[2];
    const float* Wih = (const float*)d_in[3];
    const float* Whh = (const float*)d_in[4];
    const float* bih = (const float*)d_in[5];
    const float* bhh = (const float*)d_in[6];
    const float* Wfc = (const float*)d_in[7];
    const float* bfc = (const float*)d_in[8];
    float* out = (float*)d_out;

    dim3 ggrid(T_SEQ / 64, G_DIM / 64);
    gemm_xg<<<ggrid, 256>>>(x, Wih, bih, bhh);
    lstm_rec<<<1, 128>>>(Whh, h0, c0);
    fc_out<<<1, 512>>>(Wfc, bfc, out);
}